// round 5
// baseline (speedup 1.0000x reference)
#include <cuda_runtime.h>
#include <cuda_bf16.h>

#define FEAT 64
#define MAX_USERS 200000
#define MAX_SPOTS 50000

__device__ int   g_udeg[MAX_USERS];
__device__ int   g_sdeg[MAX_SPOTS];
__device__ float g_uinv[MAX_USERS];
__device__ float g_sinv[MAX_SPOTS];

// ---------------------------------------------------------------------------
// K1: zero output (float4) and degree scratch.
// ---------------------------------------------------------------------------
__global__ void zero_kernel(float4* __restrict__ out4, int n4,
                            int* __restrict__ udeg, int nu,
                            int* __restrict__ sdeg, int ns) {
    int stride = gridDim.x * blockDim.x;
    int tid = blockIdx.x * blockDim.x + threadIdx.x;
    float4 z = make_float4(0.f, 0.f, 0.f, 0.f);
    for (int i = tid; i < n4; i += stride) out4[i] = z;
    for (int i = tid; i < nu; i += stride) udeg[i] = 0;
    for (int i = tid; i < ns; i += stride) sdeg[i] = 0;
}

// ---------------------------------------------------------------------------
// K2: integer degree counts, int4-batched (8 independent no-return atomics).
// ---------------------------------------------------------------------------
__global__ void degree_kernel(const int* __restrict__ user_idx,
                              const int* __restrict__ spot_idx,
                              int n_edges,
                              int* __restrict__ udeg,
                              int* __restrict__ sdeg) {
    int tid    = blockIdx.x * blockDim.x + threadIdx.x;
    int stride = gridDim.x * blockDim.x;
    int nvec   = n_edges >> 2;
    const int4* u4 = (const int4*)user_idx;
    const int4* s4 = (const int4*)spot_idx;
    for (int i = tid; i < nvec; i += stride) {
        int4 u = u4[i];
        int4 s = s4[i];
        atomicAdd(&udeg[u.x], 1); atomicAdd(&udeg[u.y], 1);
        atomicAdd(&udeg[u.z], 1); atomicAdd(&udeg[u.w], 1);
        atomicAdd(&sdeg[s.x], 1); atomicAdd(&sdeg[s.y], 1);
        atomicAdd(&sdeg[s.z], 1); atomicAdd(&sdeg[s.w], 1);
    }
    for (int e = (nvec << 2) + tid; e < n_edges; e += stride) {
        atomicAdd(&udeg[user_idx[e]], 1);
        atomicAdd(&sdeg[spot_idx[e]], 1);
    }
}

// ---------------------------------------------------------------------------
// K3: degree -> rsqrt weight.
// ---------------------------------------------------------------------------
__global__ void rsqrt_kernel(const int* __restrict__ udeg, float* __restrict__ uinv, int nu,
                             const int* __restrict__ sdeg, float* __restrict__ sinv, int ns) {
    int stride = gridDim.x * blockDim.x;
    int tid = blockIdx.x * blockDim.x + threadIdx.x;
    for (int i = tid; i < nu; i += stride) {
        int d = udeg[i];
        uinv[i] = rsqrtf(d > 0 ? (float)d : 1e-6f);
    }
    for (int i = tid; i < ns; i += stride) {
        int d = sdeg[i];
        sinv[i] = rsqrtf(d > 0 ? (float)d : 1e-6f);
    }
}

// ---------------------------------------------------------------------------
// Vector atomic: red.global.add.v4.f32 (sm_90+), fire-and-forget.
// ---------------------------------------------------------------------------
__device__ __forceinline__ void red_add_v4(float* p, float4 v) {
    asm volatile("red.global.add.v4.f32 [%0], {%1, %2, %3, %4};"
                 :: "l"(p), "f"(v.x), "f"(v.y), "f"(v.z), "f"(v.w)
                 : "memory");
}

// ---------------------------------------------------------------------------
// K4: single-direction scatter. Half-warp per edge; lane = float4 quarter.
// Both rsqrt weights folded into the edge contribution (no post-scale pass).
//   dst_out[d] += src_x[s] * (inv_dst[d] * inv_src[s])
// One direction per launch keeps the working set (~90MB) L2-resident.
// ---------------------------------------------------------------------------
__global__ void scatter_dir_kernel(const float* __restrict__ src_x,
                                   const int* __restrict__ dst_idx,
                                   const int* __restrict__ src_idx,
                                   const float* __restrict__ inv_dst,
                                   const float* __restrict__ inv_src,
                                   float* __restrict__ dst_out,
                                   int n_edges) {
    int gtid   = blockIdx.x * blockDim.x + threadIdx.x;
    int warp   = gtid >> 5;
    int lane   = threadIdx.x & 31;
    int half   = lane >> 4;          // which edge of the pair
    int hl     = lane & 15;          // lane within half-warp
    int col    = hl * 4;
    int nwarp  = (gridDim.x * blockDim.x) >> 5;
    int stride = nwarp * 2;

    for (int e = warp * 2 + half; e < n_edges; e += stride) {
        int d = __ldg(&dst_idx[e]);      // uniform within half-warp
        int s = __ldg(&src_idx[e]);
        float w = __ldg(&inv_dst[d]) * __ldg(&inv_src[s]);

        float4 v = *reinterpret_cast<const float4*>(src_x + (size_t)s * FEAT + col);
        red_add_v4(dst_out + (size_t)d * FEAT + col,
                   make_float4(v.x * w, v.y * w, v.z * w, v.w * w));
    }
}

// ---------------------------------------------------------------------------
extern "C" void kernel_launch(void* const* d_in, const int* in_sizes, int n_in,
                              void* d_out, int out_size) {
    const float* user_x   = (const float*)d_in[0];
    const float* spot_x   = (const float*)d_in[1];
    const int*   user_idx = (const int*)d_in[2];
    const int*   spot_idx = (const int*)d_in[3];

    int n_users = in_sizes[0] / FEAT;
    int n_spots = in_sizes[1] / FEAT;
    int n_edges = in_sizes[2];

    float* out      = (float*)d_out;
    float* user_out = out;
    float* spot_out = out + (size_t)n_users * FEAT;

    int *udeg, *sdeg;
    float *uinv, *sinv;
    cudaGetSymbolAddress((void**)&udeg, g_udeg);
    cudaGetSymbolAddress((void**)&sdeg, g_sdeg);
    cudaGetSymbolAddress((void**)&uinv, g_uinv);
    cudaGetSymbolAddress((void**)&sinv, g_sinv);

    const int TPB = 256;
    const int BLK = 148 * 8;

    zero_kernel<<<BLK, TPB>>>((float4*)out, out_size / 4, udeg, n_users, sdeg, n_spots);
    degree_kernel<<<BLK, TPB>>>(user_idx, spot_idx, n_edges, udeg, sdeg);
    rsqrt_kernel<<<BLK, TPB>>>(udeg, uinv, n_users, sdeg, sinv, n_spots);

    // Pass A: user_out <- spot_x   (working set: spot_x 13MB + user_out 51MB + idx 26MB)
    scatter_dir_kernel<<<148 * 16, TPB>>>(spot_x, user_idx, spot_idx,
                                          uinv, sinv, user_out, n_edges);
    // Pass B: spot_out <- user_x   (working set: user_x 51MB + spot_out 13MB + idx 26MB)
    scatter_dir_kernel<<<148 * 16, TPB>>>(user_x, spot_idx, user_idx,
                                          sinv, uinv, spot_out, n_edges);
}